// round 14
// baseline (speedup 1.0000x reference)
#include <cuda_runtime.h>
#include <cuda_fp16.h>
#include <cstdint>

#define SQ 2048
#define NB 16
#define HD 64
#define MASKW (SQ*SQ/32)        /* 131,072 words */
#define KEEPW (NB*SQ*SQ/32)     /* 2,097,152 words = 8 MB */
#define BATCHW (SQ*SQ/32)       /* 131,072 keep words per batch */
#define NELEM (NB*SQ*HD)        /* 2,097,152 per tensor */

#define NGEN 152                /* one gen CTA per SM (GB300: 152 SMs) */
#define NFLASH (NB*(SQ/128))    /* 256 flash CTAs */

__device__ uint32_t g_mbits[MASKW];
__device__ uint32_t g_keep[KEEPW];
__device__ int      g_done[NB];
__device__ __half g_qh[NELEM];  /* q/8 fp16, [b*SQ+row][d]  */
__device__ __half g_kh[NELEM];  /* k fp16,   [b*SQ+key][d]  */
__device__ __half g_vt[NELEM];  /* v fp16 transposed: [b][d][key] */

// threefry2x32 partitionable, key=(0,42): keep decision for counter i.
// (bits>>9) < 7549747  <=>  bits < 0xE6666600   (R11 version: proven fastest)
__device__ __forceinline__ bool tf_keep(uint32_t i) {
    const uint32_t ks1 = 42u;
    const uint32_t ks2 = 0x1BD11BDAu ^ 42u;
    uint32_t x0 = 0u, x1 = i + ks1;
#define TFR(r) { x0 += x1; x1 = __funnelshift_l(x1, x1, r); x1 ^= x0; }
    TFR(13) TFR(15) TFR(26) TFR(6)
    x0 += ks1; x1 += ks2 + 1u;
    TFR(17) TFR(29) TFR(16) TFR(24)
    x0 += ks2; x1 += 2u;
    TFR(13) TFR(15) TFR(26) TFR(6)
    x1 += ks1 + 3u;
    TFR(17) TFR(29) TFR(16) TFR(24)
    x0 += ks1; x1 += ks2 + 4u;
    TFR(13) TFR(15) TFR(26) TFR(6)
    x0 += ks2; x1 += 5u;
#undef TFR
    return (x0 ^ x1) < 0xE6666600u;
}

// ===========================================================================
// prep kernels (run before the fused kernel; also reset g_done each replay)
// ===========================================================================
__global__ void round_qk_kernel(const float4* __restrict__ q,
                                const float4* __restrict__ k) {
    int i = blockIdx.x * blockDim.x + threadIdx.x;
    if (blockIdx.x == 0 && threadIdx.x < NB) g_done[threadIdx.x] = 0;
    float4 t = __ldg(q + i);
    __half2 h0 = __floats2half2_rn(t.x * 0.125f, t.y * 0.125f);
    __half2 h1 = __floats2half2_rn(t.z * 0.125f, t.w * 0.125f);
    uint32_t* qd = (uint32_t*)g_qh + i * 2;
    qd[0] = *(uint32_t*)&h0;
    qd[1] = *(uint32_t*)&h1;
    t = __ldg(k + i);
    h0 = __floats2half2_rn(t.x, t.y);
    h1 = __floats2half2_rn(t.z, t.w);
    uint32_t* kd = (uint32_t*)g_kh + i * 2;
    kd[0] = *(uint32_t*)&h0;
    kd[1] = *(uint32_t*)&h1;
}

__global__ void vt_kernel(const float* __restrict__ v) {
    __shared__ __half s[64][65];
    const int b  = blockIdx.x >> 5;
    const int kt = blockIdx.x & 31;
    const int t  = threadIdx.x;
    {
        const int key = t >> 2;
        const int c   = (t & 3) * 16;
        const float4* src = (const float4*)(v + ((size_t)(b * SQ + kt * 64 + key)) * HD + c);
#pragma unroll
        for (int j = 0; j < 4; j++) {
            float4 f = __ldg(src + j);
            s[key][c + j * 4 + 0] = __float2half_rn(f.x);
            s[key][c + j * 4 + 1] = __float2half_rn(f.y);
            s[key][c + j * 4 + 2] = __float2half_rn(f.z);
            s[key][c + j * 4 + 3] = __float2half_rn(f.w);
        }
    }
    __syncthreads();
    {
        const int d  = t >> 2;
        const int kc = (t & 3) * 16;
        uint32_t* dst = (uint32_t*)g_vt + ((((size_t)(b * 64 + d)) * SQ + kt * 64 + kc) >> 1);
#pragma unroll
        for (int j = 0; j < 8; j++) {
            __half2 h = __halves2half2(s[kc + 2 * j][d], s[kc + 2 * j + 1][d]);
            dst[j] = *(uint32_t*)&h;
        }
    }
}

__global__ void pack_mask_kernel(const int* __restrict__ mask) {
    uint32_t lane = threadIdx.x & 31u;
    uint32_t warp = (blockIdx.x * blockDim.x + threadIdx.x) >> 5;
    uint32_t nw   = (gridDim.x * blockDim.x) >> 5;
    for (uint32_t w = warp * 4u; w < MASKW; w += nw * 4u) {
        int v0 = __ldg(mask + (size_t)w * 32 + lane);
        int v1 = __ldg(mask + (size_t)(w + 1) * 32 + lane);
        int v2 = __ldg(mask + (size_t)(w + 2) * 32 + lane);
        int v3 = __ldg(mask + (size_t)(w + 3) * 32 + lane);
        uint4 b;
        b.x = __ballot_sync(0xffffffffu, v0 != 0);
        b.y = __ballot_sync(0xffffffffu, v1 != 0);
        b.z = __ballot_sync(0xffffffffu, v2 != 0);
        b.w = __ballot_sync(0xffffffffu, v3 != 0);
        if (lane == 0) *(uint4*)(g_mbits + w) = b;
    }
}

// ===========================================================================
// Fused producer/consumer kernel.
// bids [0, NGEN): gen CTAs — threefry keep bits, batch 0..15 in order,
//   release g_done[b] after each batch. One gen CTA per SM (4 warps =
//   1 per SMSP, enough ILP to saturate the alu pipe).
// bids [NGEN, NGEN+NFLASH): flash CTAs — fp16 mma flash, acquire-spin on
//   g_done[batch] before the main loop. Placement (bid % nSM) pairs one
//   gen + one flash CTA per SM; gen exits free slots for wave-2 flash.
// ===========================================================================

#define KP32 36
#define KROWB (KP32*4)
#define KTILEB (64*KROWB)
#define BUFB (2*KTILEB)
#define SMEM_BYTES (2*BUFB)              /* 36,864 B static */

#define CP16(dst, src) asm volatile("cp.async.cg.shared.global [%0], [%1], 16;" :: "r"(dst), "l"(src) : "memory")
#define CP_COMMIT()    asm volatile("cp.async.commit_group;" ::: "memory")
#define CP_WAIT0()     asm volatile("cp.async.wait_group 0;" ::: "memory")

__device__ __forceinline__ uint32_t s2u(const void* p) {
    uint32_t a;
    asm("{ .reg .u64 t; cvta.to.shared.u64 t, %1; cvt.u32.u64 %0, t; }" : "=r"(a) : "l"(p));
    return a;
}

__device__ __forceinline__ void mma_f16(float c[4], const uint32_t a[4],
                                        uint32_t b0, uint32_t b1) {
    asm volatile(
        "mma.sync.aligned.m16n8k16.row.col.f32.f16.f16.f32 "
        "{%0,%1,%2,%3}, {%4,%5,%6,%7}, {%8,%9}, {%0,%1,%2,%3};"
        : "+f"(c[0]), "+f"(c[1]), "+f"(c[2]), "+f"(c[3])
        : "r"(a[0]), "r"(a[1]), "r"(a[2]), "r"(a[3]), "r"(b0), "r"(b1));
}

__global__ void __launch_bounds__(128, 2) fused_kernel(float* __restrict__ out)
{
    __shared__ char smem[SMEM_BYTES];
    const int tid  = threadIdx.x;
    const int bidx = blockIdx.x;

    if (bidx < NGEN) {
        // ===================== GEN: threefry keep bits =====================
        const uint32_t lane = tid & 31u;
        const uint32_t gw   = (uint32_t)bidx * 4u + (uint32_t)(tid >> 5);
        const uint32_t nwp  = NGEN * 4u;

        for (int b = 0; b < NB; b++) {
            const uint32_t base = (uint32_t)b * BATCHW;
            const uint32_t end  = base + BATCHW;
            for (uint32_t w = base + gw * 4u; w < end; w += nwp * 4u) {
                uint32_t i0 = w * 32u + lane;
                bool c0 = tf_keep(i0);
                bool c1 = tf_keep(i0 + 32u);
                bool c2 = tf_keep(i0 + 64u);
                bool c3 = tf_keep(i0 + 96u);
                uint4 bb;
                bb.x = __ballot_sync(0xffffffffu, c0);
                bb.y = __ballot_sync(0xffffffffu, c1);
                bb.z = __ballot_sync(0xffffffffu, c2);
                bb.w = __ballot_sync(0xffffffffu, c3);
                if (lane == 0) *(uint4*)(g_keep + w) = bb;
            }
            __syncthreads();
            if (tid == 0) {
                asm volatile("red.release.gpu.global.add.s32 [%0], 1;"
                             :: "l"(g_done + b) : "memory");
            }
        }
        return;
    }

    // ========================= FLASH consumer =========================
    const uint32_t sb = s2u(smem);
    const int fb   = bidx - NGEN;
    const int wid  = tid >> 5;
    const int lane = tid & 31;
    const int g    = lane >> 2;
    const int e    = lane & 3;
    const int b    = fb >> 4;
    const int qt   = fb & 15;
    const int qbw  = qt * 128 + wid * 32;
    const float INVK = (float)(1.0 / 0.9);

    const int srow = tid >> 1;
    const int shf  = tid & 1;
    const __half* ksrc = g_kh + ((size_t)(b * SQ + srow)) * HD + shf * 32;
    const __half* vsrc = g_vt + ((size_t)(b * 64 + srow)) * SQ + shf * 32;
    const uint32_t kdst = sb + (uint32_t)(srow * KROWB + shf * 64);
    const uint32_t vdst = kdst + KTILEB;

    uint32_t qa[2][4][4];
#pragma unroll
    for (int mf = 0; mf < 2; mf++) {
        const uint32_t* q0 = (const uint32_t*)g_qh + ((size_t)(b * SQ + qbw + mf * 16 + g)) * 32;
        const uint32_t* q1 = q0 + 8 * 32;
#pragma unroll
        for (int kb = 0; kb < 4; kb++) {
            qa[mf][kb][0] = __ldg(q0 + kb * 8 + e);
            qa[mf][kb][1] = __ldg(q1 + kb * 8 + e);
            qa[mf][kb][2] = __ldg(q0 + kb * 8 + e + 4);
            qa[mf][kb][3] = __ldg(q1 + kb * 8 + e + 4);
        }
    }

    float dpv[2][8][4];
#pragma unroll
    for (int mf = 0; mf < 2; mf++)
#pragma unroll
        for (int nf = 0; nf < 8; nf++)
#pragma unroll
            for (int j = 0; j < 4; j++) dpv[mf][nf][j] = 0.0f;
    float l[4] = {0.f, 0.f, 0.f, 0.f};

#pragma unroll
    for (int c = 0; c < 4; c++) {
        CP16(kdst + c * 16, (const char*)ksrc + c * 16);
        CP16(vdst + c * 16, (const char*)vsrc + c * 16);
    }
    CP_COMMIT();

    // ---- wait for this batch's keep bits (producer flag) ----
    if (tid == 0) {
        int v;
        while (true) {
            asm volatile("ld.acquire.gpu.global.s32 %0, [%1];"
                         : "=r"(v) : "l"(g_done + b) : "memory");
            if (v >= NGEN) break;
            __nanosleep(256);
        }
    }
    CP_WAIT0();
    __syncthreads();

    for (int it = 0; it < 32; it++) {
        const int cur = it & 1;
        const uint32_t* Ksw = (const uint32_t*)(smem + cur * BUFB);
        const uint32_t* Vtw = Ksw + KTILEB / 4;

        if (it < 31) {
            const uint32_t boff = (uint32_t)((cur ^ 1) * BUFB);
            const char* kn = (const char*)(ksrc + (size_t)(it + 1) * 64 * HD);
            const char* vn = (const char*)(vsrc + (it + 1) * 64);
#pragma unroll
            for (int c = 0; c < 4; c++) {
                CP16(kdst + boff + c * 16, kn + c * 16);
                CP16(vdst + boff + c * 16, vn + c * 16);
            }
            CP_COMMIT();
        }

        uint2 mwv[4], kwv[4];
#pragma unroll
        for (int r = 0; r < 4; r++) {
            int row = qbw + (r >> 1) * 16 + (r & 1) * 8 + g;
            mwv[r] = *(const uint2*)(g_mbits + (size_t)row * (SQ / 32) + it * 2);
            kwv[r] = *(const uint2*)(g_keep + ((size_t)(b * SQ + row)) * (SQ / 32) + it * 2);
        }

        uint32_t pa[2][4][4];
#pragma unroll
        for (int np = 0; np < 4; np++) {
            float c[2][2][4];
#pragma unroll
            for (int s = 0; s < 2; s++)
#pragma unroll
                for (int mf = 0; mf < 2; mf++)
#pragma unroll
                    for (int j = 0; j < 4; j++) c[s][mf][j] = 0.0f;
#pragma unroll
            for (int kb = 0; kb < 4; kb++) {
                const uint32_t* kr0 = Ksw + ((np * 2 + 0) * 8 + g) * KP32 + kb * 8 + e;
                const uint32_t* kr1 = Ksw + ((np * 2 + 1) * 8 + g) * KP32 + kb * 8 + e;
                uint32_t b00 = kr0[0], b01 = kr0[4];
                uint32_t b10 = kr1[0], b11 = kr1[4];
                mma_f16(c[0][0], qa[0][kb], b00, b01);
                mma_f16(c[0][1], qa[1][kb], b00, b01);
                mma_f16(c[1][0], qa[0][kb], b10, b11);
                mma_f16(c[1][1], qa[1][kb], b10, b11);
            }
#pragma unroll
            for (int s = 0; s < 2; s++) {
                const int nf = np * 2 + s;
                const int bit = (nf & 3) * 8 + 2 * e;
#pragma unroll
                for (int mf = 0; mf < 2; mf++) {
#pragma unroll
                    for (int hf = 0; hf < 2; hf++) {
                        const int r = mf * 2 + hf;
                        uint32_t mword = (nf < 4) ? mwv[r].x : mwv[r].y;
                        uint32_t kword = (nf < 4) ? kwv[r].x : kwv[r].y;
                        float s0 = c[s][mf][hf * 2 + 0];
                        float s1 = c[s][mf][hf * 2 + 1];
                        float p0 = ((mword >> bit) & 1u) ? __expf(s0) : 0.0f;
                        float p1 = ((mword >> (bit + 1)) & 1u) ? __expf(s1) : 0.0f;
                        l[r] += p0 + p1;
                        float d0 = ((kword >> bit) & 1u) ? p0 * INVK : 0.0f;
                        float d1 = ((kword >> (bit + 1)) & 1u) ? p1 * INVK : 0.0f;
                        __half2 h = __floats2half2_rn(d0, d1);
                        pa[mf][np][(s << 1) | hf] = *(uint32_t*)&h;
                    }
                }
            }
        }

#pragma unroll
        for (int kb = 0; kb < 4; kb++) {
#pragma unroll
            for (int nf2 = 0; nf2 < 8; nf2++) {
                const uint32_t* vr = Vtw + (nf2 * 8 + g) * KP32 + kb * 8 + e;
                uint32_t b0 = vr[0], b1 = vr[4];
                mma_f16(dpv[0][nf2], pa[0][kb], b0, b1);
                mma_f16(dpv[1][nf2], pa[1][kb], b0, b1);
            }
        }

        if (it < 31) CP_WAIT0();
        __syncthreads();
    }

#pragma unroll
    for (int r = 0; r < 4; r++) {
        l[r] += __shfl_xor_sync(0xffffffffu, l[r], 1);
        l[r] += __shfl_xor_sync(0xffffffffu, l[r], 2);
    }
#pragma unroll
    for (int r = 0; r < 4; r++) {
        float invl = 1.0f / l[r];
        int row = qbw + (r >> 1) * 16 + (r & 1) * 8 + g;
        float* op = out + ((size_t)(b * SQ + row)) * HD + 2 * e;
#pragma unroll
        for (int nf2 = 0; nf2 < 8; nf2++) {
            float2 t;
            t.x = dpv[r >> 1][nf2][(r & 1) * 2 + 0] * invl;
            t.y = dpv[r >> 1][nf2][(r & 1) * 2 + 1] * invl;
            *(float2*)(op + nf2 * 8) = t;
        }
    }
}

// ===========================================================================
extern "C" void kernel_launch(void* const* d_in, const int* in_sizes, int n_in,
                              void* d_out, int out_size) {
    const float* q = (const float*)d_in[0];
    const float* k = (const float*)d_in[1];
    const float* v = (const float*)d_in[2];
    const int* mask = (const int*)d_in[3];
    float* out = (float*)d_out;

    round_qk_kernel<<<NELEM / 4 / 256, 256>>>((const float4*)q, (const float4*)k);
    vt_kernel<<<NB * 32, 256>>>(v);
    pack_mask_kernel<<<1024, 256>>>(mask);
    fused_kernel<<<NGEN + NFLASH, 128>>>(out);
}

// round 15
// speedup vs baseline: 1.5886x; 1.5886x over previous
#include <cuda_runtime.h>
#include <cuda_fp16.h>
#include <cstdint>

#define SQ 2048
#define NB 16
#define HD 64
#define MASKW (SQ*SQ/32)        /* 131,072 words */
#define KEEPW (NB*SQ*SQ/32)     /* 2,097,152 words = 8 MB */
#define NELEM (NB*SQ*HD)        /* 2,097,152 per tensor */

__device__ uint32_t g_mbits[MASKW];
__device__ uint32_t g_keep[KEEPW];
__device__ __half g_qh[NELEM];  /* q/8 fp16, [b*SQ+row][d]  */
__device__ __half g_kh[NELEM];  /* k fp16,   [b*SQ+key][d]  */
__device__ __half g_vt[NELEM];  /* v fp16 transposed: [b][d][key] */

/* runtime 1 so ptxas emits genuine IMAD (fma pipe) for every threefry add
   instead of IADD3 (alu pipe); rotates stay SHF+LOP3 on alu. */
__device__ uint32_t g_one = 1u;

// ===========================================================================
// gen_keep: threefry2x32 partitionable, key=(0,42).
// (bits>>9) < 7549747  <=>  bits < 0xE6666600
// All adds forced to IMAD.LO (fma pipe) via runtime multiplier 'one';
// rotate = SHF + fused-xor LOP3 (2 alu). Per eval: ~44 alu + ~31 fma
// (was ~60 alu + ~17 fma) -> alu floor 161 -> ~117 us.
// ===========================================================================
__global__ void __launch_bounds__(256) gen_keep_kernel() {
    uint32_t lane = threadIdx.x & 31u;
    uint32_t warp = (blockIdx.x * blockDim.x + threadIdx.x) >> 5;
    uint32_t nw   = (gridDim.x * blockDim.x) >> 5;

    const uint32_t one = g_one;
    const uint32_t ks1 = 42u;
    const uint32_t ks2 = 0x1BD11BDAu ^ 42u;

/* add on the fma pipe: IMAD(a, one, b) */
#define FADD(a, b) ((a) * one + (b))
/* round: x0 = x0 + x1 (fma); x1 = rotl(x1,r) ^ x0 (SHF + LOP3, alu) */
#define TFR(x0, x1, r) { x0 = FADD(x0, x1); x1 = __funnelshift_l(x1, x1, r) ^ x0; }
#define TFEVAL(i, res) {                                                      \
    uint32_t x0 = 0u, x1 = FADD((i), ks1);                                    \
    TFR(x0, x1, 13) TFR(x0, x1, 15) TFR(x0, x1, 26) TFR(x0, x1, 6)            \
    x0 = FADD(x0, ks1); x1 = FADD(x1, ks2 + 1u);                              \
    TFR(x0, x1, 17) TFR(x0, x1, 29) TFR(x0, x1, 16) TFR(x0, x1, 24)           \
    x0 = FADD(x0, ks2); x1 = FADD(x1, 2u);                                    \
    TFR(x0, x1, 13) TFR(x0, x1, 15) TFR(x0, x1, 26) TFR(x0, x1, 6)            \
    x1 = FADD(x1, ks1 + 3u);                                                  \
    TFR(x0, x1, 17) TFR(x0, x1, 29) TFR(x0, x1, 16) TFR(x0, x1, 24)           \
    x0 = FADD(x0, ks1); x1 = FADD(x1, ks2 + 4u);                              \
    TFR(x0, x1, 13) TFR(x0, x1, 15) TFR(x0, x1, 26) TFR(x0, x1, 6)            \
    x0 = FADD(x0, ks2); x1 = FADD(x1, 5u);                                    \
    res = (x0 ^ x1) < 0xE6666600u;                                            \
}

    for (uint32_t w = warp * 4u; w < KEEPW; w += nw * 4u) {
        uint32_t i0 = w * 32u + lane;
        bool c0, c1, c2, c3;
        TFEVAL(i0,       c0);
        TFEVAL(i0 + 32u, c1);
        TFEVAL(i0 + 64u, c2);
        TFEVAL(i0 + 96u, c3);
        uint4 bb;
        bb.x = __ballot_sync(0xffffffffu, c0);
        bb.y = __ballot_sync(0xffffffffu, c1);
        bb.z = __ballot_sync(0xffffffffu, c2);
        bb.w = __ballot_sync(0xffffffffu, c3);
        if (lane == 0) *(uint4*)(g_keep + w) = bb;
    }
#undef FADD
#undef TFR
#undef TFEVAL
}

// ===========================================================================
// convert q (scaled 1/8) and k to fp16
// ===========================================================================
__global__ void round_qk_kernel(const float4* __restrict__ q,
                                const float4* __restrict__ k) {
    int i = blockIdx.x * blockDim.x + threadIdx.x;
    float4 t = __ldg(q + i);
    __half2 h0 = __floats2half2_rn(t.x * 0.125f, t.y * 0.125f);
    __half2 h1 = __floats2half2_rn(t.z * 0.125f, t.w * 0.125f);
    uint32_t* qd = (uint32_t*)g_qh + i * 2;
    qd[0] = *(uint32_t*)&h0;
    qd[1] = *(uint32_t*)&h1;
    t = __ldg(k + i);
    h0 = __floats2half2_rn(t.x, t.y);
    h1 = __floats2half2_rn(t.z, t.w);
    uint32_t* kd = (uint32_t*)g_kh + i * 2;
    kd[0] = *(uint32_t*)&h0;
    kd[1] = *(uint32_t*)&h1;
}

// ===========================================================================
// transpose v to fp16 g_vt[b][d][key]
// ===========================================================================
__global__ void vt_kernel(const float* __restrict__ v) {
    __shared__ __half s[64][65];
    const int b  = blockIdx.x >> 5;
    const int kt = blockIdx.x & 31;
    const int t  = threadIdx.x;
    {
        const int key = t >> 2;
        const int c   = (t & 3) * 16;
        const float4* src = (const float4*)(v + ((size_t)(b * SQ + kt * 64 + key)) * HD + c);
#pragma unroll
        for (int j = 0; j < 4; j++) {
            float4 f = __ldg(src + j);
            s[key][c + j * 4 + 0] = __float2half_rn(f.x);
            s[key][c + j * 4 + 1] = __float2half_rn(f.y);
            s[key][c + j * 4 + 2] = __float2half_rn(f.z);
            s[key][c + j * 4 + 3] = __float2half_rn(f.w);
        }
    }
    __syncthreads();
    {
        const int d  = t >> 2;
        const int kc = (t & 3) * 16;
        uint32_t* dst = (uint32_t*)g_vt + ((((size_t)(b * 64 + d)) * SQ + kt * 64 + kc) >> 1);
#pragma unroll
        for (int j = 0; j < 8; j++) {
            __half2 h = __halves2half2(s[kc + 2 * j][d], s[kc + 2 * j + 1][d]);
            dst[j] = *(uint32_t*)&h;
        }
    }
}

// ===========================================================================
// pack attn_mask into bits (bit=1 -> unmasked)
// ===========================================================================
__global__ void pack_mask_kernel(const int* __restrict__ mask) {
    uint32_t lane = threadIdx.x & 31u;
    uint32_t warp = (blockIdx.x * blockDim.x + threadIdx.x) >> 5;
    uint32_t nw   = (gridDim.x * blockDim.x) >> 5;
    for (uint32_t w = warp * 4u; w < MASKW; w += nw * 4u) {
        int v0 = __ldg(mask + (size_t)w * 32 + lane);
        int v1 = __ldg(mask + (size_t)(w + 1) * 32 + lane);
        int v2 = __ldg(mask + (size_t)(w + 2) * 32 + lane);
        int v3 = __ldg(mask + (size_t)(w + 3) * 32 + lane);
        uint4 b;
        b.x = __ballot_sync(0xffffffffu, v0 != 0);
        b.y = __ballot_sync(0xffffffffu, v1 != 0);
        b.z = __ballot_sync(0xffffffffu, v2 != 0);
        b.w = __ballot_sync(0xffffffffu, v3 != 0);
        if (lane == 0) *(uint4*)(g_mbits + w) = b;
    }
}

// ===========================================================================
// fp16 m16n8k16 flash attention (R11-exact, proven 95.5us).
// ===========================================================================

#define KP32 36
#define KROWB (KP32*4)
#define KTILEB (64*KROWB)
#define BUFB (2*KTILEB)
#define SMEM_BYTES (2*BUFB)

#define CP16(dst, src) asm volatile("cp.async.cg.shared.global [%0], [%1], 16;" :: "r"(dst), "l"(src) : "memory")
#define CP_COMMIT()    asm volatile("cp.async.commit_group;" ::: "memory")
#define CP_WAIT0()     asm volatile("cp.async.wait_group 0;" ::: "memory")

__device__ __forceinline__ uint32_t s2u(const void* p) {
    uint32_t a;
    asm("{ .reg .u64 t; cvta.to.shared.u64 t, %1; cvt.u32.u64 %0, t; }" : "=r"(a) : "l"(p));
    return a;
}

__device__ __forceinline__ void mma_f16(float c[4], const uint32_t a[4],
                                        uint32_t b0, uint32_t b1) {
    asm volatile(
        "mma.sync.aligned.m16n8k16.row.col.f32.f16.f16.f32 "
        "{%0,%1,%2,%3}, {%4,%5,%6,%7}, {%8,%9}, {%0,%1,%2,%3};"
        : "+f"(c[0]), "+f"(c[1]), "+f"(c[2]), "+f"(c[3])
        : "r"(a[0]), "r"(a[1]), "r"(a[2]), "r"(a[3]), "r"(b0), "r"(b1));
}

__global__ void __launch_bounds__(128, 2) flash_mma_kernel(float* __restrict__ out)
{
    extern __shared__ char smem[];
    const uint32_t sb = s2u(smem);

    const int tid  = threadIdx.x;
    const int wid  = tid >> 5;
    const int lane = tid & 31;
    const int g    = lane >> 2;
    const int e    = lane & 3;
    const int b    = blockIdx.x >> 4;
    const int qt   = blockIdx.x & 15;
    const int qbw  = qt * 128 + wid * 32;
    const float INVK = (float)(1.0 / 0.9);

    const int srow = tid >> 1;
    const int shf  = tid & 1;
    const __half* ksrc = g_kh + ((size_t)(b * SQ + srow)) * HD + shf * 32;
    const __half* vsrc = g_vt + ((size_t)(b * 64 + srow)) * SQ + shf * 32;
    const uint32_t kdst = sb + (uint32_t)(srow * KROWB + shf * 64);
    const uint32_t vdst = kdst + KTILEB;

    uint32_t qa[2][4][4];
#pragma unroll
    for (int mf = 0; mf < 2; mf++) {
        const uint32_t* q0 = (const uint32_t*)g_qh + ((size_t)(b * SQ + qbw + mf * 16 + g)) * 32;
        const uint32_t* q1 = q0 + 8 * 32;
#pragma unroll
        for (int kb = 0; kb < 4; kb++) {
            qa[mf][kb][0] = __ldg(q0 + kb * 8 + e);
            qa[mf][kb][1] = __ldg(q1 + kb * 8 + e);
            qa[mf][kb][2] = __ldg(q0 + kb * 8 + e + 4);
            qa[mf][kb][3] = __ldg(q1 + kb * 8 + e + 4);
        }
    }

    float dpv[2][8][4];
#pragma unroll
    for (int mf = 0; mf < 2; mf++)
#pragma unroll
        for (int nf = 0; nf < 8; nf++)
#pragma unroll
            for (int j = 0; j < 4; j++) dpv[mf][nf][j] = 0.0f;
    float l[4] = {0.f, 0.f, 0.f, 0.f};

#pragma unroll
    for (int c = 0; c < 4; c++) {
        CP16(kdst + c * 16, (const char*)ksrc + c * 16);
        CP16(vdst + c * 16, (const char*)vsrc + c * 16);
    }
    CP_COMMIT(); CP_WAIT0();
    __syncthreads();

    for (int it = 0; it < 32; it++) {
        const int cur = it & 1;
        const uint32_t* Ksw = (const uint32_t*)(smem + cur * BUFB);
        const uint32_t* Vtw = Ksw + KTILEB / 4;

        if (it < 31) {
            const uint32_t boff = (uint32_t)((cur ^ 1) * BUFB);
            const char* kn = (const char*)(ksrc + (size_t)(it + 1) * 64 * HD);
            const char* vn = (const char*)(vsrc + (it + 1) * 64);
#pragma unroll
            for (int c = 0; c < 4; c++) {
                CP16(kdst + boff + c * 16, kn + c * 16);
                CP16(vdst + boff + c * 16, vn + c * 16);
            }
            CP_COMMIT();
        }

        uint2 mwv[4], kwv[4];
#pragma unroll
        for (int r = 0; r < 4; r++) {
            int row = qbw + (r >> 1) * 16 + (r & 1) * 8 + g;
            mwv[r] = *(const uint2*)(g_mbits + (size_t)row * (SQ / 32) + it * 2);
            kwv[r] = *(const uint2*)(g_keep + ((size_t)(b * SQ + row)) * (SQ / 32) + it * 2);
        }

        uint32_t pa[2][4][4];
#pragma unroll
        for (int np = 0; np < 4; np++) {
            float c[2][2][4];
#pragma unroll
            for (int s = 0; s < 2; s++)
#pragma unroll
                for (int mf = 0; mf < 2; mf++)
#pragma unroll
                    for (int j = 0; j < 4; j++) c[s][mf][j] = 0.0f;
#pragma unroll
            for (int kb = 0; kb < 4; kb++) {
                const uint32_t* kr0 = Ksw + ((np * 2 + 0) * 8 + g) * KP32 + kb * 8 + e;
                const uint32_t* kr1 = Ksw + ((np * 2 + 1) * 8 + g) * KP32 + kb * 8 + e;
                uint32_t b00 = kr0[0], b01 = kr0[4];
                uint32_t b10 = kr1[0], b11 = kr1[4];
                mma_f16(c[0][0], qa[0][kb], b00, b01);
                mma_f16(c[0][1], qa[1][kb], b00, b01);
                mma_f16(c[1][0], qa[0][kb], b10, b11);
                mma_f16(c[1][1], qa[1][kb], b10, b11);
            }
#pragma unroll
            for (int s = 0; s < 2; s++) {
                const int nf = np * 2 + s;
                const int bit = (nf & 3) * 8 + 2 * e;
#pragma unroll
                for (int mf = 0; mf < 2; mf++) {
#pragma unroll
                    for (int hf = 0; hf < 2; hf++) {
                        const int r = mf * 2 + hf;
                        uint32_t mword = (nf < 4) ? mwv[r].x : mwv[r].y;
                        uint32_t kword = (nf < 4) ? kwv[r].x : kwv[r].y;
                        float s0 = c[s][mf][hf * 2 + 0];
                        float s1 = c[s][mf][hf * 2 + 1];
                        float p0 = ((mword >> bit) & 1u) ? __expf(s0) : 0.0f;
                        float p1 = ((mword >> (bit + 1)) & 1u) ? __expf(s1) : 0.0f;
                        l[r] += p0 + p1;
                        float d0 = ((kword >> bit) & 1u) ? p0 * INVK : 0.0f;
                        float d1 = ((kword >> (bit + 1)) & 1u) ? p1 * INVK : 0.0f;
                        __half2 h = __floats2half2_rn(d0, d1);
                        pa[mf][np][(s << 1) | hf] = *(uint32_t*)&h;
                    }
                }
            }
        }

#pragma unroll
        for (int kb = 0; kb < 4; kb++) {
#pragma unroll
            for (int nf2 = 0; nf2 < 8; nf2++) {
                const uint32_t* vr = Vtw + (nf2 * 8 + g) * KP32 + kb * 8 + e;
                uint32_t b0 = vr[0], b1 = vr[4];
                mma_f16(dpv[0][nf2], pa[0][kb], b0, b1);
                mma_f16(dpv[1][nf2], pa[1][kb], b0, b1);
            }
        }

        if (it < 31) CP_WAIT0();
        __syncthreads();
    }

#pragma unroll
    for (int r = 0; r < 4; r++) {
        l[r] += __shfl_xor_sync(0xffffffffu, l[r], 1);
        l[r] += __shfl_xor_sync(0xffffffffu, l[r], 2);
    }
#pragma unroll
    for (int r = 0; r < 4; r++) {
        float invl = 1.0f / l[r];
        int row = qbw + (r >> 1) * 16 + (r & 1) * 8 + g;
        float* op = out + ((size_t)(b * SQ + row)) * HD + 2 * e;
#pragma unroll
        for (int nf2 = 0; nf2 < 8; nf2++) {
            float2 t;
            t.x = dpv[r >> 1][nf2][(r & 1) * 2 + 0] * invl;
            t.y = dpv[r >> 1][nf2][(r & 1) * 2 + 1] * invl;
            *(float2*)(op + nf2 * 8) = t;
        }
    }
}

// ===========================================================================
extern "C" void kernel_launch(void* const* d_in, const int* in_sizes, int n_in,
                              void* d_out, int out_size) {
    const float* q = (const float*)d_in[0];
    const float* k = (const float*)d_in[1];
    const float* v = (const float*)d_in[2];
    const int* mask = (const int*)d_in[3];
    float* out = (float*)d_out;

    round_qk_kernel<<<NELEM / 4 / 256, 256>>>((const float4*)q, (const float4*)k);
    vt_kernel<<<NB * 32, 256>>>(v);
    pack_mask_kernel<<<1024, 256>>>(mask);
    gen_keep_kernel<<<2048, 256>>>();
    flash_mma_kernel<<<NB * (SQ / 128), 128, SMEM_BYTES>>>(out);
}

// round 16
// speedup vs baseline: 2.0388x; 1.2834x over previous
#include <cuda_runtime.h>
#include <cuda_fp16.h>
#include <cstdint>

#define SQ 2048
#define NB 16
#define HD 64
#define MASKW (SQ*SQ/32)        /* 131,072 words */
#define KEEPW (NB*SQ*SQ/32)     /* 2,097,152 words = 8 MB */
#define NELEM (NB*SQ*HD)        /* 2,097,152 per tensor */
#define NSLOT (SQ*(SQ/32))      /* 131,072 (row,word) slots */

__device__ uint32_t g_mbits[MASKW];
__device__ uint32_t g_keep[KEEPW];
__device__ __half g_qh[NELEM];  /* q/8 fp16, [b*SQ+row][d]  */
__device__ __half g_kh[NELEM];  /* k fp16,   [b*SQ+key][d]  */
__device__ __half g_vt[NELEM];  /* v fp16 transposed: [b][d][key] */

// threefry2x32 partitionable, key=(0,42): keep decision for counter i.
// (bits>>9) < 7549747  <=>  bits < 0xE6666600
__device__ __forceinline__ uint32_t tf_keep(uint32_t i) {
    const uint32_t ks1 = 42u;
    const uint32_t ks2 = 0x1BD11BDAu ^ 42u;
    uint32_t x0 = 0u, x1 = i + ks1;
#define TFR(r) { x0 += x1; x1 = __funnelshift_l(x1, x1, r) ^ x0; }
    TFR(13) TFR(15) TFR(26) TFR(6)
    x0 += ks1; x1 += ks2 + 1u;
    TFR(17) TFR(29) TFR(16) TFR(24)
    x0 += ks2; x1 += 2u;
    TFR(13) TFR(15) TFR(26) TFR(6)
    x1 += ks1 + 3u;
    TFR(17) TFR(29) TFR(16) TFR(24)
    x0 += ks1; x1 += ks2 + 4u;
    TFR(13) TFR(15) TFR(26) TFR(6)
    x0 += ks2; x1 += 5u;
#undef TFR
    return ((x0 ^ x1) < 0xE6666600u) ? 1u : 0u;
}

// ===========================================================================
// gen_keep, mask-gated: keep bits are only computed where the attn-mask bit
// is 1 (elsewhere they are don't-care: flash computes p=0 there regardless).
// Warp layout: lanes 0-15 = batches 0-15 of slot 2t, lanes 16-31 of slot
// 2t+1. Each 16-lane group shares one mask word -> convergent ffs loop;
// evals drop to ~popcount(mask)/32 ~ 55% (incl. max over the two groups).
// MUST run after pack_mask_kernel.
// ===========================================================================
__global__ void __launch_bounds__(256) gen_keep_kernel() {
    const uint32_t lane = threadIdx.x & 31u;
    const uint32_t warp = (blockIdx.x * blockDim.x + threadIdx.x) >> 5;
    const uint32_t nwp  = (gridDim.x * blockDim.x) >> 5;
    const uint32_t b    = lane & 15u;

    for (uint32_t t = warp; t < (NSLOT / 2); t += nwp) {
        const uint32_t s   = t * 2u + (lane >> 4);        // (row,word) slot
        const uint32_t row = s >> 6;
        const uint32_t w   = s & 63u;
        uint32_t m = g_mbits[s];                          // shared in group
        const uint32_t ctr0 = (((b << 11) + row) << 11) + w * 32u;
        uint32_t bits = 0u;
        while (m) {
            const uint32_t bit = (uint32_t)(__ffs(m) - 1);
            m &= m - 1u;
            bits |= tf_keep(ctr0 + bit) << bit;
        }
        g_keep[((b << 11) + row) * 64u + w] = bits;
    }
}

// ===========================================================================
// convert q (scaled 1/8) and k to fp16
// ===========================================================================
__global__ void round_qk_kernel(const float4* __restrict__ q,
                                const float4* __restrict__ k) {
    int i = blockIdx.x * blockDim.x + threadIdx.x;
    float4 t = __ldg(q + i);
    __half2 h0 = __floats2half2_rn(t.x * 0.125f, t.y * 0.125f);
    __half2 h1 = __floats2half2_rn(t.z * 0.125f, t.w * 0.125f);
    uint32_t* qd = (uint32_t*)g_qh + i * 2;
    qd[0] = *(uint32_t*)&h0;
    qd[1] = *(uint32_t*)&h1;
    t = __ldg(k + i);
    h0 = __floats2half2_rn(t.x, t.y);
    h1 = __floats2half2_rn(t.z, t.w);
    uint32_t* kd = (uint32_t*)g_kh + i * 2;
    kd[0] = *(uint32_t*)&h0;
    kd[1] = *(uint32_t*)&h1;
}

// ===========================================================================
// transpose v to fp16 g_vt[b][d][key]
// ===========================================================================
__global__ void vt_kernel(const float* __restrict__ v) {
    __shared__ __half s[64][65];
    const int b  = blockIdx.x >> 5;
    const int kt = blockIdx.x & 31;
    const int t  = threadIdx.x;
    {
        const int key = t >> 2;
        const int c   = (t & 3) * 16;
        const float4* src = (const float4*)(v + ((size_t)(b * SQ + kt * 64 + key)) * HD + c);
#pragma unroll
        for (int j = 0; j < 4; j++) {
            float4 f = __ldg(src + j);
            s[key][c + j * 4 + 0] = __float2half_rn(f.x);
            s[key][c + j * 4 + 1] = __float2half_rn(f.y);
            s[key][c + j * 4 + 2] = __float2half_rn(f.z);
            s[key][c + j * 4 + 3] = __float2half_rn(f.w);
        }
    }
    __syncthreads();
    {
        const int d  = t >> 2;
        const int kc = (t & 3) * 16;
        uint32_t* dst = (uint32_t*)g_vt + ((((size_t)(b * 64 + d)) * SQ + kt * 64 + kc) >> 1);
#pragma unroll
        for (int j = 0; j < 8; j++) {
            __half2 h = __halves2half2(s[kc + 2 * j][d], s[kc + 2 * j + 1][d]);
            dst[j] = *(uint32_t*)&h;
        }
    }
}

// ===========================================================================
// pack attn_mask into bits (bit=1 -> unmasked)
// ===========================================================================
__global__ void pack_mask_kernel(const int* __restrict__ mask) {
    uint32_t lane = threadIdx.x & 31u;
    uint32_t warp = (blockIdx.x * blockDim.x + threadIdx.x) >> 5;
    uint32_t nw   = (gridDim.x * blockDim.x) >> 5;
    for (uint32_t w = warp * 4u; w < MASKW; w += nw * 4u) {
        int v0 = __ldg(mask + (size_t)w * 32 + lane);
        int v1 = __ldg(mask + (size_t)(w + 1) * 32 + lane);
        int v2 = __ldg(mask + (size_t)(w + 2) * 32 + lane);
        int v3 = __ldg(mask + (size_t)(w + 3) * 32 + lane);
        uint4 b;
        b.x = __ballot_sync(0xffffffffu, v0 != 0);
        b.y = __ballot_sync(0xffffffffu, v1 != 0);
        b.z = __ballot_sync(0xffffffffu, v2 != 0);
        b.w = __ballot_sync(0xffffffffu, v3 != 0);
        if (lane == 0) *(uint4*)(g_mbits + w) = b;
    }
}

// ===========================================================================
// fp16 m16n8k16 flash attention (R11-exact, proven 95.5us).
// ===========================================================================

#define KP32 36
#define KROWB (KP32*4)
#define KTILEB (64*KROWB)
#define BUFB (2*KTILEB)
#define SMEM_BYTES (2*BUFB)

#define CP16(dst, src) asm volatile("cp.async.cg.shared.global [%0], [%1], 16;" :: "r"(dst), "l"(src) : "memory")
#define CP_COMMIT()    asm volatile("cp.async.commit_group;" ::: "memory")
#define CP_WAIT0()     asm volatile("cp.async.wait_group 0;" ::: "memory")

__device__ __forceinline__ uint32_t s2u(const void* p) {
    uint32_t a;
    asm("{ .reg .u64 t; cvta.to.shared.u64 t, %1; cvt.u32.u64 %0, t; }" : "=r"(a) : "l"(p));
    return a;
}

__device__ __forceinline__ void mma_f16(float c[4], const uint32_t a[4],
                                        uint32_t b0, uint32_t b1) {
    asm volatile(
        "mma.sync.aligned.m16n8k16.row.col.f32.f16.f16.f32 "
        "{%0,%1,%2,%3}, {%4,%5,%6,%7}, {%8,%9}, {%0,%1,%2,%3};"
        : "+f"(c[0]), "+f"(c[1]), "+f"(c[2]), "+f"(c[3])
        : "r"(a[0]), "r"(a[1]), "r"(a[2]), "r"(a[3]), "r"(b0), "r"(b1));
}

__global__ void __launch_bounds__(128, 2) flash_mma_kernel(float* __restrict__ out)
{
    extern __shared__ char smem[];
    const uint32_t sb = s2u(smem);

    const int tid  = threadIdx.x;
    const int wid  = tid >> 5;
    const int lane = tid & 31;
    const int g    = lane >> 2;
    const int e    = lane & 3;
    const int b    = blockIdx.x >> 4;
    const int qt   = blockIdx.x & 15;
    const int qbw  = qt * 128 + wid * 32;
    const float INVK = (float)(1.0 / 0.9);

    const int srow = tid >> 1;
    const int shf  = tid & 1;
    const __half* ksrc = g_kh + ((size_t)(b * SQ + srow)) * HD + shf * 32;
    const __half* vsrc = g_vt + ((size_t)(b * 64 + srow)) * SQ + shf * 32;
    const uint32_t kdst = sb + (uint32_t)(srow * KROWB + shf * 64);
    const uint32_t vdst = kdst + KTILEB;

    uint32_t qa[2][4][4];
#pragma unroll
    for (int mf = 0; mf < 2; mf++) {
        const uint32_t* q0 = (const uint32_t*)g_qh + ((size_t)(b * SQ + qbw + mf * 16 + g)) * 32;
        const uint32_t* q1 = q0 + 8 * 32;
#pragma unroll
        for (int kb = 0; kb < 4; kb++) {
            qa[mf][kb][0] = __ldg(q0 + kb * 8 + e);
            qa[mf][kb][1] = __ldg(q1 + kb * 8 + e);
            qa[mf][kb][2] = __ldg(q0 + kb * 8 + e + 4);
            qa[mf][kb][3] = __ldg(q1 + kb * 8 + e + 4);
        }
    }

    float dpv[2][8][4];
#pragma unroll
    for (int mf = 0; mf < 2; mf++)
#pragma unroll
        for (int nf = 0; nf < 8; nf++)
#pragma unroll
            for (int j = 0; j < 4; j++) dpv[mf][nf][j] = 0.0f;
    float l[4] = {0.f, 0.f, 0.f, 0.f};

#pragma unroll
    for (int c = 0; c < 4; c++) {
        CP16(kdst + c * 16, (const char*)ksrc + c * 16);
        CP16(vdst + c * 16, (const char*)vsrc + c * 16);
    }
    CP_COMMIT(); CP_WAIT0();
    __syncthreads();

    for (int it = 0; it < 32; it++) {
        const int cur = it & 1;
        const uint32_t* Ksw = (const uint32_t*)(smem + cur * BUFB);
        const uint32_t* Vtw = Ksw + KTILEB / 4;

        if (it < 31) {
            const uint32_t boff = (uint32_t)((cur ^ 1) * BUFB);
            const char* kn = (const char*)(ksrc + (size_t)(it + 1) * 64 * HD);
            const char* vn = (const char*)(vsrc + (it + 1) * 64);
#pragma unroll
            for (int c = 0; c < 4; c++) {
                CP16(kdst + boff + c * 16, kn + c * 16);
                CP16(vdst + boff + c * 16, vn + c * 16);
            }
            CP_COMMIT();
        }

        uint2 mwv[4], kwv[4];
#pragma unroll
        for (int r = 0; r < 4; r++) {
            int row = qbw + (r >> 1) * 16 + (r & 1) * 8 + g;
            mwv[r] = *(const uint2*)(g_mbits + (size_t)row * (SQ / 32) + it * 2);
            kwv[r] = *(const uint2*)(g_keep + ((size_t)(b * SQ + row)) * (SQ / 32) + it * 2);
        }

        uint32_t pa[2][4][4];
#pragma unroll
        for (int np = 0; np < 4; np++) {
            float c[2][2][4];
#pragma unroll
            for (int s = 0; s < 2; s++)
#pragma unroll
                for (int mf = 0; mf < 2; mf++)
#pragma unroll
                    for (int j = 0; j < 4; j++) c[s][mf][j] = 0.0f;
#pragma unroll
            for (int kb = 0; kb < 4; kb++) {
                const uint32_t* kr0 = Ksw + ((np * 2 + 0) * 8 + g) * KP32 + kb * 8 + e;
                const uint32_t* kr1 = Ksw + ((np * 2 + 1) * 8 + g) * KP32 + kb * 8 + e;
                uint32_t b00 = kr0[0], b01 = kr0[4];
                uint32_t b10 = kr1[0], b11 = kr1[4];
                mma_f16(c[0][0], qa[0][kb], b00, b01);
                mma_f16(c[0][1], qa[1][kb], b00, b01);
                mma_f16(c[1][0], qa[0][kb], b10, b11);
                mma_f16(c[1][1], qa[1][kb], b10, b11);
            }
#pragma unroll
            for (int s = 0; s < 2; s++) {
                const int nf = np * 2 + s;
                const int bit = (nf & 3) * 8 + 2 * e;
#pragma unroll
                for (int mf = 0; mf < 2; mf++) {
#pragma unroll
                    for (int hf = 0; hf < 2; hf++) {
                        const int r = mf * 2 + hf;
                        uint32_t mword = (nf < 4) ? mwv[r].x : mwv[r].y;
                        uint32_t kword = (nf < 4) ? kwv[r].x : kwv[r].y;
                        float s0 = c[s][mf][hf * 2 + 0];
                        float s1 = c[s][mf][hf * 2 + 1];
                        float p0 = ((mword >> bit) & 1u) ? __expf(s0) : 0.0f;
                        float p1 = ((mword >> (bit + 1)) & 1u) ? __expf(s1) : 0.0f;
                        l[r] += p0 + p1;
                        float d0 = ((kword >> bit) & 1u) ? p0 * INVK : 0.0f;
                        float d1 = ((kword >> (bit + 1)) & 1u) ? p1 * INVK : 0.0f;
                        __half2 h = __floats2half2_rn(d0, d1);
                        pa[mf][np][(s << 1) | hf] = *(uint32_t*)&h;
                    }
                }
            }
        }

#pragma unroll
        for (int kb = 0; kb < 4; kb++) {
#pragma unroll
            for (int nf2 = 0; nf2 < 8; nf2++) {
                const uint32_t* vr = Vtw + (nf2 * 8 + g) * KP32 + kb * 8 + e;
                uint32_t b0 = vr[0], b1 = vr[4];
                mma_f16(dpv[0][nf2], pa[0][kb], b0, b1);
                mma_f16(dpv[1][nf2], pa[1][kb], b0, b1);
            }
        }

        if (it < 31) CP_WAIT0();
        __syncthreads();
    }

#pragma unroll
    for (int r = 0; r < 4; r++) {
        l[r] += __shfl_xor_sync(0xffffffffu, l[r], 1);
        l[r] += __shfl_xor_sync(0xffffffffu, l[r], 2);
    }
#pragma unroll
    for (int r = 0; r < 4; r++) {
        float invl = 1.0f / l[r];
        int row = qbw + (r >> 1) * 16 + (r & 1) * 8 + g;
        float* op = out + ((size_t)(b * SQ + row)) * HD + 2 * e;
#pragma unroll
        for (int nf2 = 0; nf2 < 8; nf2++) {
            float2 t;
            t.x = dpv[r >> 1][nf2][(r & 1) * 2 + 0] * invl;
            t.y = dpv[r >> 1][nf2][(r & 1) * 2 + 1] * invl;
            *(float2*)(op + nf2 * 8) = t;
        }
    }
}

// ===========================================================================
extern "C" void kernel_launch(void* const* d_in, const int* in_sizes, int n_in,
                              void* d_out, int out_size) {
    const float* q = (const float*)d_in[0];
    const float* k = (const float*)d_in[1];
    const float* v = (const float*)d_in[2];
    const int* mask = (const int*)d_in[3];
    float* out = (float*)d_out;

    pack_mask_kernel<<<1024, 256>>>(mask);       /* must precede gen_keep */
    round_qk_kernel<<<NELEM / 4 / 256, 256>>>((const float4*)q, (const float4*)k);
    vt_kernel<<<NB * 32, 256>>>(v);
    gen_keep_kernel<<<2048, 256>>>();
    flash_mma_kernel<<<NB * (SQ / 128), 128, SMEM_BYTES>>>(out);
}

// round 17
// speedup vs baseline: 2.0826x; 1.0215x over previous
#include <cuda_runtime.h>
#include <cuda_fp16.h>
#include <cstdint>

#define SQ 2048
#define NB 16
#define HD 64
#define MASKW (SQ*SQ/32)        /* 131,072 words */
#define KEEPW (NB*SQ*SQ/32)     /* 2,097,152 words = 8 MB */
#define NELEM (NB*SQ*HD)        /* 2,097,152 per tensor */
#define NSLOT (SQ*(SQ/32))      /* 131,072 (row,word) slots */

__device__ uint32_t g_mbits[MASKW];
__device__ uint32_t g_keep[KEEPW];
__device__ __half g_qh[NELEM];  /* q/8 fp16, [b*SQ+row][d]  */
__device__ __half g_kh[NELEM];  /* k fp16,   [b*SQ+key][d]  */
__device__ __half g_vt[NELEM];  /* v fp16 transposed: [b][d][key] */

// threefry2x32 partitionable, key=(0,42): keep decision for counter i.
// (bits>>9) < 7549747  <=>  bits < 0xE6666600
__device__ __forceinline__ uint32_t tf_keep(uint32_t i) {
    const uint32_t ks1 = 42u;
    const uint32_t ks2 = 0x1BD11BDAu ^ 42u;
    uint32_t x0 = 0u, x1 = i + ks1;
#define TFR(r) { x0 += x1; x1 = __funnelshift_l(x1, x1, r) ^ x0; }
    TFR(13) TFR(15) TFR(26) TFR(6)
    x0 += ks1; x1 += ks2 + 1u;
    TFR(17) TFR(29) TFR(16) TFR(24)
    x0 += ks2; x1 += 2u;
    TFR(13) TFR(15) TFR(26) TFR(6)
    x1 += ks1 + 3u;
    TFR(17) TFR(29) TFR(16) TFR(24)
    x0 += ks1; x1 += ks2 + 4u;
    TFR(13) TFR(15) TFR(26) TFR(6)
    x0 += ks2; x1 += 5u;
#undef TFR
    return ((x0 ^ x1) < 0xE6666600u) ? 1u : 0u;
}

// ===========================================================================
// Fused prep: block-range dispatch (MUST run after pack_mask_kernel).
//  [0, GEN_B):    mask-gated threefry keep bits. One (row,word) slot per
//                 warp: lanes 0-15 = 16 batches x even-indexed set bits,
//                 lanes 16-31 = same batches x odd-indexed set bits.
//                 iterations = ceil(popcount/2); halves combined via shfl.
//  [GEN_B, +RQK): q/k fp16 convert (memory-bound, hides under gen)
//  [.., +VT):     v fp16 transpose
// ===========================================================================
#define GEN_B 2048
#define RQK_B 2048
#define VT_B  512
#define PREP_BLOCKS (GEN_B + RQK_B + VT_B)

__global__ void __launch_bounds__(256) prep_kernel(
    const float4* __restrict__ q, const float4* __restrict__ k,
    const float* __restrict__ v)
{
    __shared__ __half s[64][65];
    const int bid = blockIdx.x;
    const int tid = threadIdx.x;

    if (bid < GEN_B) {
        // ---------------- mask-gated gen keep bits ----------------
        const uint32_t lane  = tid & 31u;
        const uint32_t grp   = lane >> 4;
        const uint32_t batch = lane & 15u;
        const uint32_t warp  = ((uint32_t)bid * 256u + (uint32_t)tid) >> 5;
        const uint32_t nwp   = (GEN_B * 256u) >> 5;

        for (uint32_t sl = warp; sl < NSLOT; sl += nwp) {
            const uint32_t row = sl >> 6;
            const uint32_t w   = sl & 63u;
            uint32_t m = g_mbits[sl];
            const uint32_t ctr0 = (((batch << 11) + row) << 11) + w * 32u;
            uint32_t bits = 0u;
            while (m) {
                const int b0 = __ffs(m) - 1;
                m &= m - 1u;
                const int b1 = m ? (__ffs(m) - 1) : -1;
                m &= m - 1u;                       /* m==0 -> stays 0 */
                const int mybit = grp ? b1 : b0;
                if (mybit >= 0)
                    bits |= tf_keep(ctr0 + (uint32_t)mybit) << mybit;
            }
            bits |= __shfl_xor_sync(0xffffffffu, bits, 16);
            if (grp == 0)
                g_keep[((batch << 11) + row) * 64u + w] = bits;
        }
    } else if (bid < GEN_B + RQK_B) {
        // ---------------- q/k fp16 convert ----------------
        int i = (bid - GEN_B) * 256 + tid;         /* 0..NELEM/4-1 */
        float4 t = __ldg(q + i);
        __half2 h0 = __floats2half2_rn(t.x * 0.125f, t.y * 0.125f);
        __half2 h1 = __floats2half2_rn(t.z * 0.125f, t.w * 0.125f);
        uint32_t* qd = (uint32_t*)g_qh + i * 2;
        qd[0] = *(uint32_t*)&h0;
        qd[1] = *(uint32_t*)&h1;
        t = __ldg(k + i);
        h0 = __floats2half2_rn(t.x, t.y);
        h1 = __floats2half2_rn(t.z, t.w);
        uint32_t* kd = (uint32_t*)g_kh + i * 2;
        kd[0] = *(uint32_t*)&h0;
        kd[1] = *(uint32_t*)&h1;
    } else {
        // ---------------- v fp16 transpose ----------------
        const int vb = bid - GEN_B - RQK_B;        /* 0..511 */
        const int b  = vb >> 5;
        const int kt = vb & 31;
        {
            const int key = tid >> 2;
            const int c   = (tid & 3) * 16;
            const float4* src = (const float4*)(v + ((size_t)(b * SQ + kt * 64 + key)) * HD + c);
#pragma unroll
            for (int j = 0; j < 4; j++) {
                float4 f = __ldg(src + j);
                s[key][c + j * 4 + 0] = __float2half_rn(f.x);
                s[key][c + j * 4 + 1] = __float2half_rn(f.y);
                s[key][c + j * 4 + 2] = __float2half_rn(f.z);
                s[key][c + j * 4 + 3] = __float2half_rn(f.w);
            }
        }
        __syncthreads();
        {
            const int d  = tid >> 2;
            const int kc = (tid & 3) * 16;
            uint32_t* dst = (uint32_t*)g_vt + ((((size_t)(b * 64 + d)) * SQ + kt * 64 + kc) >> 1);
#pragma unroll
            for (int j = 0; j < 8; j++) {
                __half2 h = __halves2half2(s[kc + 2 * j][d], s[kc + 2 * j + 1][d]);
                dst[j] = *(uint32_t*)&h;
            }
        }
    }
}

// ===========================================================================
// pack attn_mask into bits (bit=1 -> unmasked)
// ===========================================================================
__global__ void pack_mask_kernel(const int* __restrict__ mask) {
    uint32_t lane = threadIdx.x & 31u;
    uint32_t warp = (blockIdx.x * blockDim.x + threadIdx.x) >> 5;
    uint32_t nw   = (gridDim.x * blockDim.x) >> 5;
    for (uint32_t w = warp * 4u; w < MASKW; w += nw * 4u) {
        int v0 = __ldg(mask + (size_t)w * 32 + lane);
        int v1 = __ldg(mask + (size_t)(w + 1) * 32 + lane);
        int v2 = __ldg(mask + (size_t)(w + 2) * 32 + lane);
        int v3 = __ldg(mask + (size_t)(w + 3) * 32 + lane);
        uint4 b;
        b.x = __ballot_sync(0xffffffffu, v0 != 0);
        b.y = __ballot_sync(0xffffffffu, v1 != 0);
        b.z = __ballot_sync(0xffffffffu, v2 != 0);
        b.w = __ballot_sync(0xffffffffu, v3 != 0);
        if (lane == 0) *(uint4*)(g_mbits + w) = b;
    }
}

// ===========================================================================
// fp16 m16n8k16 flash attention (R11-exact, proven).
// ===========================================================================

#define KP32 36
#define KROWB (KP32*4)
#define KTILEB (64*KROWB)
#define BUFB (2*KTILEB)
#define SMEM_BYTES (2*BUFB)

#define CP16(dst, src) asm volatile("cp.async.cg.shared.global [%0], [%1], 16;" :: "r"(dst), "l"(src) : "memory")
#define CP_COMMIT()    asm volatile("cp.async.commit_group;" ::: "memory")
#define CP_WAIT0()     asm volatile("cp.async.wait_group 0;" ::: "memory")

__device__ __forceinline__ uint32_t s2u(const void* p) {
    uint32_t a;
    asm("{ .reg .u64 t; cvta.to.shared.u64 t, %1; cvt.u32.u64 %0, t; }" : "=r"(a) : "l"(p));
    return a;
}

__device__ __forceinline__ void mma_f16(float c[4], const uint32_t a[4],
                                        uint32_t b0, uint32_t b1) {
    asm volatile(
        "mma.sync.aligned.m16n8k16.row.col.f32.f16.f16.f32 "
        "{%0,%1,%2,%3}, {%4,%5,%6,%7}, {%8,%9}, {%0,%1,%2,%3};"
        : "+f"(c[0]), "+f"(c[1]), "+f"(c[2]), "+f"(c[3])
        : "r"(a[0]), "r"(a[1]), "r"(a[2]), "r"(a[3]), "r"(b0), "r"(b1));
}

__global__ void __launch_bounds__(128, 2) flash_mma_kernel(float* __restrict__ out)
{
    extern __shared__ char smem[];
    const uint32_t sb = s2u(smem);

    const int tid  = threadIdx.x;
    const int wid  = tid >> 5;
    const int lane = tid & 31;
    const int g    = lane >> 2;
    const int e    = lane & 3;
    const int b    = blockIdx.x >> 4;
    const int qt   = blockIdx.x & 15;
    const int qbw  = qt * 128 + wid * 32;
    const float INVK = (float)(1.0 / 0.9);

    const int srow = tid >> 1;
    const int shf  = tid & 1;
    const __half* ksrc = g_kh + ((size_t)(b * SQ + srow)) * HD + shf * 32;
    const __half* vsrc = g_vt + ((size_t)(b * 64 + srow)) * SQ + shf * 32;
    const uint32_t kdst = sb + (uint32_t)(srow * KROWB + shf * 64);
    const uint32_t vdst = kdst + KTILEB;

    uint32_t qa[2][4][4];
#pragma unroll
    for (int mf = 0; mf < 2; mf++) {
        const uint32_t* q0 = (const uint32_t*)g_qh + ((size_t)(b * SQ + qbw + mf * 16 + g)) * 32;
        const uint32_t* q1 = q0 + 8 * 32;
#pragma unroll
        for (int kb = 0; kb < 4; kb++) {
            qa[mf][kb][0] = __ldg(q0 + kb * 8 + e);
            qa[mf][kb][1] = __ldg(q1 + kb * 8 + e);
            qa[mf][kb][2] = __ldg(q0 + kb * 8 + e + 4);
            qa[mf][kb][3] = __ldg(q1 + kb * 8 + e + 4);
        }
    }

    float dpv[2][8][4];
#pragma unroll
    for (int mf = 0; mf < 2; mf++)
#pragma unroll
        for (int nf = 0; nf < 8; nf++)
#pragma unroll
            for (int j = 0; j < 4; j++) dpv[mf][nf][j] = 0.0f;
    float l[4] = {0.f, 0.f, 0.f, 0.f};

#pragma unroll
    for (int c = 0; c < 4; c++) {
        CP16(kdst + c * 16, (const char*)ksrc + c * 16);
        CP16(vdst + c * 16, (const char*)vsrc + c * 16);
    }
    CP_COMMIT(); CP_WAIT0();
    __syncthreads();

    for (int it = 0; it < 32; it++) {
        const int cur = it & 1;
        const uint32_t* Ksw = (const uint32_t*)(smem + cur * BUFB);
        const uint32_t* Vtw = Ksw + KTILEB / 4;

        if (it < 31) {
            const uint32_t boff = (uint32_t)((cur ^ 1) * BUFB);
            const char* kn = (const char*)(ksrc + (size_t)(it + 1) * 64 * HD);
            const char* vn = (const char*)(vsrc + (it + 1) * 64);
#pragma unroll
            for (int c = 0; c < 4; c++) {
                CP16(kdst + boff + c * 16, kn + c * 16);
                CP16(vdst + boff + c * 16, vn + c * 16);
            }
            CP_COMMIT();
        }

        uint2 mwv[4], kwv[4];
#pragma unroll
        for (int r = 0; r < 4; r++) {
            int row = qbw + (r >> 1) * 16 + (r & 1) * 8 + g;
            mwv[r] = *(const uint2*)(g_mbits + (size_t)row * (SQ / 32) + it * 2);
            kwv[r] = *(const uint2*)(g_keep + ((size_t)(b * SQ + row)) * (SQ / 32) + it * 2);
        }

        uint32_t pa[2][4][4];
#pragma unroll
        for (int np = 0; np < 4; np++) {
            float c[2][2][4];
#pragma unroll
            for (int s = 0; s < 2; s++)
#pragma unroll
                for (int mf = 0; mf < 2; mf++)
#pragma unroll
                    for (int j = 0; j < 4; j++) c[s][mf][j] = 0.0f;
#pragma unroll
            for (int kb = 0; kb < 4; kb++) {
                const uint32_t* kr0 = Ksw + ((np * 2 + 0) * 8 + g) * KP32 + kb * 8 + e;
                const uint32_t* kr1 = Ksw + ((np * 2 + 1) * 8 + g) * KP32 + kb * 8 + e;
                uint32_t b00 = kr0[0], b01 = kr0[4];
                uint32_t b10 = kr1[0], b11 = kr1[4];
                mma_f16(c[0][0], qa[0][kb], b00, b01);
                mma_f16(c[0][1], qa[1][kb], b00, b01);
                mma_f16(c[1][0], qa[0][kb], b10, b11);
                mma_f16(c[1][1], qa[1][kb], b10, b11);
            }
#pragma unroll
            for (int s = 0; s < 2; s++) {
                const int nf = np * 2 + s;
                const int bit = (nf & 3) * 8 + 2 * e;
#pragma unroll
                for (int mf = 0; mf < 2; mf++) {
#pragma unroll
                    for (int hf = 0; hf < 2; hf++) {
                        const int r = mf * 2 + hf;
                        uint32_t mword = (nf < 4) ? mwv[r].x : mwv[r].y;
                        uint32_t kword = (nf < 4) ? kwv[r].x : kwv[r].y;
                        float s0 = c[s][mf][hf * 2 + 0];
                        float s1 = c[s][mf][hf * 2 + 1];
                        float p0 = ((mword >> bit) & 1u) ? __expf(s0) : 0.0f;
                        float p1 = ((mword >> (bit + 1)) & 1u) ? __expf(s1) : 0.0f;
                        l[r] += p0 + p1;
                        float d0 = ((kword >> bit) & 1u) ? p0 * INVK : 0.0f;
                        float d1 = ((kword >> (bit + 1)) & 1u) ? p1 * INVK : 0.0f;
                        __half2 h = __floats2half2_rn(d0, d1);
                        pa[mf][np][(s << 1) | hf] = *(uint32_t*)&h;
                    }
                }
            }
        }

#pragma unroll
        for (int kb = 0; kb < 4; kb++) {
#pragma unroll
            for (int nf2 = 0; nf2 < 8; nf2++) {
                const uint32_t* vr = Vtw + (nf2 * 8 + g) * KP32 + kb * 8 + e;
                uint32_t b0 = vr[0], b1 = vr[4];
                mma_f16(dpv[0][nf2], pa[0][kb], b0, b1);
                mma_f16(dpv[1][nf2], pa[1][kb], b0, b1);
            }
        }

        if (it < 31) CP_WAIT0();
        __syncthreads();
    }

#pragma unroll
    for (int r = 0; r < 4; r++) {
        l[r] += __shfl_xor_sync(0xffffffffu, l[r], 1);
        l[r] += __shfl_xor_sync(0xffffffffu, l[r], 2);
    }
#pragma unroll
    for (int r = 0; r < 4; r++) {
        float invl = 1.0f / l[r];
        int row = qbw + (r >> 1) * 16 + (r & 1) * 8 + g;
        float* op = out + ((size_t)(b * SQ + row)) * HD + 2 * e;
#pragma unroll
        for (int nf2 = 0; nf2 < 8; nf2++) {
            float2 t;
            t.x = dpv[r >> 1][nf2][(r & 1) * 2 + 0] * invl;
            t.y = dpv[r >> 1][nf2][(r & 1) * 2 + 1] * invl;
            *(float2*)(op + nf2 * 8) = t;
        }
    }
}

// ===========================================================================
extern "C" void kernel_launch(void* const* d_in, const int* in_sizes, int n_in,
                              void* d_out, int out_size) {
    const float* q = (const float*)d_in[0];
    const float* k = (const float*)d_in[1];
    const float* v = (const float*)d_in[2];
    const int* mask = (const int*)d_in[3];
    float* out = (float*)d_out;

    pack_mask_kernel<<<1024, 256>>>(mask);       /* must precede prep (gen) */
    prep_kernel<<<PREP_BLOCKS, 256>>>((const float4*)q, (const float4*)k, v);
    flash_mma_kernel<<<NB * (SQ / 128), 128, SMEM_BYTES>>>(out);
}